// round 17
// baseline (speedup 1.0000x reference)
#include <cuda_runtime.h>

#define B_   1024
#define T_   1024
#define NBR  7
#define NTH  512
#define NBLK 147        // 147*7 = 1029 >= 1024

// ---- shared memory layout (float offsets) ----
// sX/sH rows: 68 floats = half0 at +0..31, half1 at +36..67 (4-word pad).
// Quarter bank groups (mod 32): x0:+0, x1:+4, h0:+8, h1:+12 -> a warp's 4
// quarter-broadcast groups cover 16 distinct banks -> 1 wavefront / LDS.128.
#define OFF_WHEAD 0         // 50*68 = 3400
#define OFF_WENCT 3400      // 23*64 = 1472 -> 4872  [k][j]
#define OFF_IN    4880      // 2 bufs * 168 = 336 -> 5216
#define OFF_X0    5248      // 7*68 = 476 -> 5724 ; 5248 % 32 == 0
#define OFF_X1    5728      // 476 -> 6204 ; % 32 == 0
#define OFF_H     6216      // 476 -> 6692 ; % 32 == 8
#define OFF_C     6704      // 448 -> 7152
#define OFF_GATE  7152      // 1792 -> 8944
#define SM_TOT    8944      // 35776 bytes

#define XP(j) ((j) < 32 ? (j) : (j) + 4)   // padded index within a 64-row

#define OFFZ ((size_t)B_ * T_ * 18)
#define OFFH ((size_t)B_ * T_ * 50)
#define OFFC (OFFH + (size_t)B_ * 64)

typedef unsigned long long ull;

__device__ __forceinline__ void fma2(ull& d, ull a, ull b) {
    asm("fma.rn.f32x2 %0, %1, %2, %0;" : "+l"(d) : "l"(a), "l"(b));
}
__device__ __forceinline__ float2 unpack2(ull v) {
    float2 r; asm("mov.b64 {%0,%1}, %2;" : "=f"(r.x), "=f"(r.y) : "l"(v)); return r;
}
__device__ __forceinline__ float sigm(float x) {
    return 1.0f / (1.0f + __expf(-x));
}

__global__ __launch_bounds__(NTH, 1)
void wm_lstm_kernel(const float* __restrict__ obs, const float* __restrict__ act,
                    const float* __restrict__ h0,  const float* __restrict__ c0,
                    const float* __restrict__ Wenc, const float* __restrict__ benc,
                    const float* __restrict__ Wih,  const float* __restrict__ Whh,
                    const float* __restrict__ bih,  const float* __restrict__ bhh,
                    const float* __restrict__ Wpred, const float* __restrict__ bpred,
                    const float* __restrict__ Wz,    const float* __restrict__ bz,
                    float* __restrict__ out) {
    __shared__ float sm[SM_TOT];

    const int tid   = threadIdx.x;
    const int bBase = blockIdx.x * NBR;

    // ---- stage head/encoder weights into shared ----
    for (int idx = tid; idx < 50 * 64; idx += NTH) {
        int o = idx >> 6, k = idx & 63;
        sm[OFF_WHEAD + o * 68 + k] = (o < 18) ? Wpred[o * 64 + k] : Wz[(o - 18) * 64 + k];
    }
    for (int idx = tid; idx < 23 * 64; idx += NTH) {
        int k = idx >> 6, j = idx & 63;
        sm[OFF_WENCT + idx] = Wenc[j * 23 + k];   // transposed [k][j]
    }
    if (tid < NBR * 64) {
        int nb = tid >> 6, j = tid & 63;
        int b = bBase + nb;
        float hv = 0.f, cv = 0.f;
        if (b < B_) { hv = h0[(size_t)b * 64 + j]; cv = c0[(size_t)b * 64 + j]; }
        sm[OFF_H + nb * 68 + XP(j)] = hv;
        sm[OFF_C + nb * 64 + j] = cv;
    }

    // ---- gate setup: thread = (gate pair u, k-quarter q), weights in regs ----
    const int q = tid & 3;              // 0,1: x halves ; 2,3: h halves
    const int u = tid >> 2;             // gate pair 0..127 -> gates 2u, 2u+1
    ull wreg2[32];                      // [e*16 + 2*k4(+1)] : 2 gates x 32 k
    {
        const float* wsrc0 = (q < 2) ? Wih : Whh;
        const int koff = (q & 1) * 32;
#pragma unroll
        for (int e = 0; e < 2; e++) {
            const float* src = wsrc0 + (2 * u + e) * 64 + koff;
#pragma unroll
            for (int k4 = 0; k4 < 8; k4++) {
                ulonglong2 tq = *(const ulonglong2*)(src + k4 * 4);
                wreg2[e * 16 + 2 * k4]     = tq.x;
                wreg2[e * 16 + 2 * k4 + 1] = tq.y;
            }
        }
    }
    float2 bg2;
    bg2.x = bih[2 * u] + bhh[2 * u];
    bg2.y = bih[2 * u + 1] + bhh[2 * u + 1];

    // ---- head constants: one thread per (nb, o), tid < 350 ----
    const bool headThr = (tid < NBR * 50);
    const int  hNb = tid / 50;
    const int  hO  = tid - hNb * 50;
    const int  hB  = bBase + hNb;
    const float bh = headThr ? ((hO < 18) ? bpred[hO] : bz[hO - 18]) : 0.f;

    // ---- in-loop encoder constants: tid >= 384, fixed column j ----
    const bool encThr = (tid >= 384);
    const int  e0 = tid - 384;              // 0..127
    const int  ej = e0 & 63;
    const int  ejp = XP(ej);
    const int  enb0 = e0 >> 6;              // 0 or 1
    const int  encCnt = (e0 < 64) ? 4 : 3;  // uniform per warp
    const float beR = benc[ej];

    // ---- input prefetch: 161 scalars/step, double-buffered sIn ----
    const int  pNb = tid / 23;
    const int  pK  = tid - pNb * 23;
    const int  pb  = bBase + pNb;
    const bool pValid = (tid < NBR * 23) && (pb < B_);
    const float* pPtr = nullptr;
    int pStep = 0;
    if (pValid) {
        if (pK < 18) { pPtr = obs + ((size_t)pb * T_) * 18 + pK;       pStep = 18; }
        else         { pPtr = act + ((size_t)pb * T_) * 5 + (pK - 18); pStep = 5;  }
    }
    // prologue input pipeline: commit in(0)->buf0, in(1)->buf1, hold in(2)
    float rIn = pValid ? pPtr[0] : 0.f;
    if (tid < NBR * 23) sm[OFF_IN + pNb * 24 + pK] = rIn;
    if (pValid) rIn = __ldg(pPtr + pStep);
    if (tid < NBR * 23) sm[OFF_IN + 168 + pNb * 24 + pK] = rIn;
    if (pValid) rIn = __ldg(pPtr + 2 * pStep);

    __syncthreads();

    // prologue: enc(0) -> sX0 (one output per thread, tid < 448)
    if (tid < NBR * 64) {
        int nb = tid >> 6, j = tid & 63;
        float a = benc[j];
#pragma unroll
        for (int k = 0; k < 23; k++)
            a = fmaf(sm[OFF_WENCT + k * 64 + j], sm[OFF_IN + nb * 24 + k], a);
        sm[OFF_X0 + nb * 68 + XP(j)] = fmaxf(a, 0.f);
    }
    __syncthreads();

    for (int t = 0; t < T_; t++) {
        // ======== MEGA phase ========
        // (i) commit in(t+2) -> sIn buf[t&1]
        if (tid < NBR * 23)
            sm[OFF_IN + (t & 1) * 168 + pNb * 24 + pK] = rIn;

        // (ii) gates(t): quarter-pair blocked, f32x2
        {
            const float* xb = sm + ((t & 1) ? OFF_X1 : OFF_X0);
            const float* vb = ((q < 2) ? xb : (sm + OFF_H)) + (q & 1) * 36;

#define GATE_CHUNK(NB0, NBC)                                                  \
            {                                                                 \
                ull acc[2 * NBC];                                             \
                _Pragma("unroll")                                             \
                for (int i = 0; i < 2 * NBC; i++) acc[i] = 0ull;              \
                _Pragma("unroll")                                             \
                for (int k4 = 0; k4 < 8; k4++) {                              \
                    const ull w00 = wreg2[2 * k4],      w01 = wreg2[2 * k4 + 1];      \
                    const ull w10 = wreg2[16 + 2 * k4], w11 = wreg2[16 + 2 * k4 + 1]; \
                    _Pragma("unroll")                                         \
                    for (int i = 0; i < NBC; i++) {                           \
                        const ulonglong2 v =                                  \
                            *(const ulonglong2*)(vb + (NB0 + i) * 68 + k4 * 4); \
                        fma2(acc[2 * i],     w00, v.x);                       \
                        fma2(acc[2 * i],     w01, v.y);                       \
                        fma2(acc[2 * i + 1], w10, v.x);                       \
                        fma2(acc[2 * i + 1], w11, v.y);                       \
                    }                                                         \
                }                                                             \
                _Pragma("unroll")                                             \
                for (int i = 0; i < NBC; i++) {                               \
                    float2 p0 = unpack2(acc[2 * i]);                          \
                    float2 p1 = unpack2(acc[2 * i + 1]);                      \
                    float s0 = p0.x + p0.y;                                   \
                    float s1 = p1.x + p1.y;                                   \
                    s0 += __shfl_xor_sync(0xffffffffu, s0, 1);                \
                    s1 += __shfl_xor_sync(0xffffffffu, s1, 1);                \
                    s0 += __shfl_xor_sync(0xffffffffu, s0, 2);                \
                    s1 += __shfl_xor_sync(0xffffffffu, s1, 2);                \
                    if (q == 0) {                                             \
                        float2 r;                                             \
                        r.x = s0 + bg2.x;                                     \
                        r.y = s1 + bg2.y;                                     \
                        *(float2*)(sm + OFF_GATE + (NB0 + i) * 256 + 2 * u) = r; \
                    }                                                         \
                }                                                             \
            }

            GATE_CHUNK(0, 4)
            GATE_CHUNK(4, 3)
#undef GATE_CHUNK
        }

        // (iii) heads(t-1): f32x2, padded-h indexing
        if (t > 0 && headThr) {
            ull a2 = 0ull;
            const float* wr = sm + OFF_WHEAD + hO * 68;
            const float* hr = sm + OFF_H + hNb * 68;
#pragma unroll
            for (int k4 = 0; k4 < 8; k4++) {
                const ulonglong2 w = *(const ulonglong2*)(wr + k4 * 4);
                const ulonglong2 h = *(const ulonglong2*)(hr + k4 * 4);
                fma2(a2, w.x, h.x);
                fma2(a2, w.y, h.y);
            }
#pragma unroll
            for (int k4 = 0; k4 < 8; k4++) {
                const ulonglong2 w = *(const ulonglong2*)(wr + 32 + k4 * 4);
                const ulonglong2 h = *(const ulonglong2*)(hr + 36 + k4 * 4);
                fma2(a2, w.x, h.x);
                fma2(a2, w.y, h.y);
            }
            float2 p = unpack2(a2);
            float a = bh + p.x + p.y;
            if (hB < B_) {
                size_t row = (size_t)hB * T_ + (t - 1);
                if (hO < 18) out[row * 18 + hO] = sigm(a);
                else         out[OFFZ + row * 32 + (hO - 18)] = a;
            }
        }

        // (iv) enc(t+1): reads sIn buf[(t+1)&1], writes sX[(t+1)&1] (padded)
        if (encThr && (t + 1 < T_)) {
            float wv[23];
#pragma unroll
            for (int k = 0; k < 23; k++)
                wv[k] = sm[OFF_WENCT + k * 64 + ej];
            const float* inb = sm + OFF_IN + ((t + 1) & 1) * 168;
            float* xw = sm + (((t + 1) & 1) ? OFF_X1 : OFF_X0);
#pragma unroll
            for (int i = 0; i < 4; i++) {
                if (i >= encCnt) break;
                int nb = (i < 3) ? (enb0 + i * 2) : 6;
                float a = beR;
#pragma unroll
                for (int k = 0; k < 23; k++)
                    a = fmaf(wv[k], inb[nb * 24 + k], a);
                xw[nb * 68 + ejp] = fmaxf(a, 0.f);
            }
        }

        // (v) prefetch in(t+3)
        {
            int tn = (t + 3 < T_) ? (t + 3) : (T_ - 1);
            if (pValid) rIn = __ldg(pPtr + (size_t)tn * pStep);
        }
        __syncthreads();

        // ======== CELL phase ========
        if (tid < NBR * 64) {
            int nb = tid >> 6, j = tid & 63;
            const float* gr = sm + OFF_GATE + nb * 256;
            float gi = gr[j], gf = gr[64 + j], gg = gr[128 + j], go = gr[192 + j];
            float cc = sm[OFF_C + nb * 64 + j];
            cc = sigm(gf) * cc + sigm(gi) * tanhf(gg);
            float hh = sigm(go) * tanhf(cc);
            sm[OFF_C + nb * 64 + j] = cc;
            sm[OFF_H + nb * 68 + XP(j)] = hh;
        }
        __syncthreads();
    }

    // ---- epilogue: heads(T-1) + final hT / cT ----
    if (headThr) {
        ull a2 = 0ull;
        const float* wr = sm + OFF_WHEAD + hO * 68;
        const float* hr = sm + OFF_H + hNb * 68;
#pragma unroll
        for (int k4 = 0; k4 < 8; k4++) {
            const ulonglong2 w = *(const ulonglong2*)(wr + k4 * 4);
            const ulonglong2 h = *(const ulonglong2*)(hr + k4 * 4);
            fma2(a2, w.x, h.x);
            fma2(a2, w.y, h.y);
        }
#pragma unroll
        for (int k4 = 0; k4 < 8; k4++) {
            const ulonglong2 w = *(const ulonglong2*)(wr + 32 + k4 * 4);
            const ulonglong2 h = *(const ulonglong2*)(hr + 36 + k4 * 4);
            fma2(a2, w.x, h.x);
            fma2(a2, w.y, h.y);
        }
        float2 p = unpack2(a2);
        float a = bh + p.x + p.y;
        if (hB < B_) {
            size_t row = (size_t)hB * T_ + (T_ - 1);
            if (hO < 18) out[row * 18 + hO] = sigm(a);
            else         out[OFFZ + row * 32 + (hO - 18)] = a;
        }
    }
    if (tid < NBR * 64) {
        int nb = tid >> 6, j = tid & 63;
        int b = bBase + nb;
        if (b < B_) {
            out[OFFH + (size_t)b * 64 + j] = sm[OFF_H + nb * 68 + XP(j)];
            out[OFFC + (size_t)b * 64 + j] = sm[OFF_C + nb * 64 + j];
        }
    }
}

extern "C" void kernel_launch(void* const* d_in, const int* in_sizes, int n_in,
                              void* d_out, int out_size) {
    (void)in_sizes; (void)n_in; (void)out_size;
    wm_lstm_kernel<<<NBLK, NTH>>>(
        (const float*)d_in[0],  (const float*)d_in[1],
        (const float*)d_in[2],  (const float*)d_in[3],
        (const float*)d_in[4],  (const float*)d_in[5],
        (const float*)d_in[6],  (const float*)d_in[7],
        (const float*)d_in[8],  (const float*)d_in[9],
        (const float*)d_in[10], (const float*)d_in[11],
        (const float*)d_in[12], (const float*)d_in[13],
        (float*)d_out);
}